// round 6
// baseline (speedup 1.0000x reference)
#include <cuda_runtime.h>
#include <cstdint>

// ---------------------------------------------------------------------------
// EMGNetQuantized: fused BinaryNet inference, XLA-CPU-matched fp32 numerics.
//   conv0: serial fp32 FMA chain per output, reduction order (ky, kx, ic)
//          [= Eigen row-major NHWC patch order], acc from 0, bias after.
//   bn sign decisions: UNFUSED mul.rn + add.rn (XLA emits no FMA contraction).
//   binary conv2 + maxpool + FC: exact integer XNOR/popcount.
// One CTA per image (8192 CTAs x 256 threads).
// ---------------------------------------------------------------------------

__device__ __align__(16) uint32_t g_w2bits[32 * 9];       // [oc][ky*3+kx], bit=ic
__device__ __align__(16) uint32_t g_wfcbits[516 * 36];    // [o][word], bit=col%32
__device__ float g_inv1[32], g_sh1[32];                   // bn1 scale/shift
__device__ float g_inv2[32], g_sh2[32];                   // bn2 scale/shift
__device__ float g_sc3[516], g_sh3[516];                  // bn3 scale/shift

__global__ void prep_kernel(const float* __restrict__ w2,
                            const float* __restrict__ wfc,
                            const float* __restrict__ g1, const float* __restrict__ be1,
                            const float* __restrict__ m1, const float* __restrict__ v1,
                            const float* __restrict__ g2, const float* __restrict__ be2,
                            const float* __restrict__ m2, const float* __restrict__ v2,
                            const float* __restrict__ g3, const float* __restrict__ be3,
                            const float* __restrict__ m3, const float* __restrict__ v3) {
    int t = blockIdx.x * blockDim.x + threadIdx.x;
    if (t < 288) {
        // pack sign(w2): w2 layout [oc][ic][3][3]
        int oc = t / 9, k = t % 9;
        uint32_t w = 0u;
        #pragma unroll 4
        for (int ic = 0; ic < 32; ic++)
            if (w2[oc * 288 + ic * 9 + k] >= 0.f) w |= (1u << ic);
        g_w2bits[t] = w;
    } else if (t < 288 + 516 * 36) {
        int j = t - 288;
        int o = j / 36, c = j % 36;
        const float* row = wfc + o * 1152 + c * 32;
        uint32_t w = 0u;
        #pragma unroll 4
        for (int b = 0; b < 32; b++)
            if (row[b] >= 0.f) w |= (1u << b);
        g_wfcbits[j] = w;
    } else if (t < 288 + 18576 + 32) {
        int c = t - (288 + 18576);
        // inv = g / sqrt(v + 1e-5), all IEEE RN, no contraction / no fast-math
        float inv = __fdiv_rn(g1[c], __fsqrt_rn(__fadd_rn(v1[c], 1e-5f)));
        g_inv1[c] = inv;
        g_sh1[c]  = __fsub_rn(be1[c], __fmul_rn(m1[c], inv));
    } else if (t < 288 + 18576 + 64) {
        int c = t - (288 + 18576 + 32);
        float inv = __fdiv_rn(g2[c], __fsqrt_rn(__fadd_rn(v2[c], 1e-5f)));
        g_inv2[c] = inv;
        g_sh2[c]  = __fsub_rn(be2[c], __fmul_rn(m2[c], inv));
    } else if (t < 288 + 18576 + 64 + 516) {
        int c = t - (288 + 18576 + 64);
        float inv = __fdiv_rn(g3[c], __fsqrt_rn(__fadd_rn(v3[c], 1e-5f)));
        g_sc3[c] = inv;
        g_sh3[c] = __fsub_rn(be3[c], __fmul_rn(m3[c], inv));
    }
}

// Padded input row stride (17 floats) to avoid bank camping in conv0 reads.
#define XPITCH 17

__global__ __launch_bounds__(256) void fused_kernel(
        const float* __restrict__ x,
        const float* __restrict__ w0,
        const float* __restrict__ b0,
        const float* __restrict__ wlast,
        const float* __restrict__ blast,
        float* __restrict__ out) {
    __shared__ float    sx[8 * 16 * XPITCH];   // input image
    __shared__ float    sw0[2304];             // conv0 weights [oc][ic][9]
    __shared__ uint32_t s1bits[196];           // conv0 sign bits, word per (y,x), bit=c
    __shared__ uint32_t sw2b[288];
    __shared__ uint32_t fcb[36];               // 1152 FC input bits
    __shared__ float    h3[516];               // bn3/htanh output

    const int tid = threadIdx.x;
    const int img = blockIdx.x;

    // ---- Phase A: stage image + weights, zero bit arrays -------------------
    {
        const float4* xin = (const float4*)(x + (size_t)img * 2048);
        #pragma unroll
        for (int i = tid; i < 512; i += 256) {
            float4 v = xin[i];
            int e  = i * 4;
            int ic = e >> 8;
            int rm = e & 255;
            int yy = rm >> 4;
            int xx = rm & 15;
            float* dst = &sx[(ic * 16 + yy) * XPITCH + xx];
            dst[0] = v.x; dst[1] = v.y; dst[2] = v.z; dst[3] = v.w;
        }
        for (int i = tid; i < 2304; i += 256) sw0[i] = w0[i];
        for (int i = tid; i < 288;  i += 256) sw2b[i] = g_w2bits[i];
        for (int i = tid; i < 196;  i += 256) s1bits[i] = 0u;
        if (tid < 36) fcb[tid] = 0u;
    }
    __syncthreads();

    // ---- Phase B: conv0, serial FMA chain per output in (ky,kx,ic) order ---
    // task = (oc, y): one thread computes one 14-wide output row; each of the
    // 14 accumulators is an independent serial chain in Eigen's k order.
    for (int task = tid; task < 448; task += 256) {
        int oc = task / 14;
        int y  = task % 14;
        float acc[14];
        #pragma unroll
        for (int i = 0; i < 14; i++) acc[i] = 0.f;

        const float* wb = &sw0[oc * 72];
        #pragma unroll
        for (int ky = 0; ky < 3; ky++) {
            #pragma unroll
            for (int kx = 0; kx < 3; kx++) {
                #pragma unroll
                for (int ic = 0; ic < 8; ic++) {
                    float w = wb[ic * 9 + ky * 3 + kx];
                    const float* row = &sx[(ic * 16 + y + ky) * XPITCH + kx];
                    #pragma unroll
                    for (int xx = 0; xx < 14; xx++)
                        acc[xx] = __fmaf_rn(row[xx], w, acc[xx]);
                }
            }
        }
        float bias = b0[oc];
        float inv  = g_inv1[oc];
        float sh   = g_sh1[oc];
        uint32_t cb = 1u << oc;
        #pragma unroll
        for (int xx = 0; xx < 14; xx++) {
            float h = __fadd_rn(acc[xx], bias);                // conv + bias
            float v = __fadd_rn(__fmul_rn(h, inv), sh);        // bn1, UNFUSED
            if (v >= 0.f)
                atomicOr(&s1bits[y * 14 + xx], cb);
        }
    }
    __syncthreads();

    // ---- Phase C: binary conv2 + integer maxpool + bn2 sign -> FC bits -----
    // task = (c, pooled y, pooled x): 32*6*6 = 1152 tasks
    for (int task = tid; task < 1152; task += 256) {
        int c  = task / 36;
        int r  = task % 36;
        int py = r / 6, px = r % 6;
        uint32_t wk[9];
        #pragma unroll
        for (int k = 0; k < 9; k++) wk[k] = sw2b[c * 9 + k];

        int maxd = -10000;
        #pragma unroll
        for (int dy = 0; dy < 2; dy++) {
            #pragma unroll
            for (int dx = 0; dx < 2; dx++) {
                int y = py * 2 + dy;
                int xx = px * 2 + dx;
                int p = 0;
                #pragma unroll
                for (int ky = 0; ky < 3; ky++) {
                    #pragma unroll
                    for (int kx = 0; kx < 3; kx++)
                        p += __popc(s1bits[(y + ky) * 14 + xx + kx] ^ wk[ky * 3 + kx]);
                }
                int d = 288 - 2 * p;               // exact integer dot
                maxd = max(maxd, d);
            }
        }
        // bn2 sign on the (integer) max, UNFUSED mul+add like the reference
        float v = __fadd_rn(__fmul_rn((float)maxd, g_inv2[c]), g_sh2[c]);
        if (v >= 0.f)
            atomicOr(&fcb[task >> 5], 1u << (task & 31));
    }
    __syncthreads();

    // ---- Phase D: binary FC (1152 -> 516, exact int) + bn3 + hardtanh ------
    for (int o = tid; o < 516; o += 256) {
        const uint4* wr = (const uint4*)&g_wfcbits[o * 36];
        int p = 0;
        #pragma unroll
        for (int q = 0; q < 9; q++) {
            uint4 wv = wr[q];
            const uint32_t* fb = &fcb[q * 4];
            p += __popc(fb[0] ^ wv.x) + __popc(fb[1] ^ wv.y)
               + __popc(fb[2] ^ wv.z) + __popc(fb[3] ^ wv.w);
        }
        float d = (float)(1152 - 2 * p);
        float h = __fadd_rn(__fmul_rn(d, g_sc3[o]), g_sh3[o]);  // bn3 UNFUSED
        h3[o] = fminf(1.f, fmaxf(-1.f, h));
    }
    __syncthreads();

    // ---- Phase E: final 516x10 GEMV (fp32) + bias --------------------------
    if (tid < 160) {
        int i = tid >> 4;       // output index 0..9
        int s = tid & 15;       // 16-lane reduction slot
        const float* wr = wlast + i * 516;
        float acc = 0.f;
        for (int j = s; j < 516; j += 16)
            acc = __fmaf_rn(h3[j], wr[j], acc);
        #pragma unroll
        for (int off = 8; off; off >>= 1)
            acc = __fadd_rn(acc, __shfl_xor_sync(0xffffffffu, acc, off, 16));
        if (s == 0)
            out[(size_t)img * 10 + i] = __fadd_rn(acc, blast[i]);
    }
}

extern "C" void kernel_launch(void* const* d_in, const int* in_sizes, int n_in,
                              void* d_out, int out_size) {
    const float* x     = (const float*)d_in[0];
    const float* w0    = (const float*)d_in[1];
    const float* b0    = (const float*)d_in[2];
    const float* g1    = (const float*)d_in[3];
    const float* be1   = (const float*)d_in[4];
    const float* m1    = (const float*)d_in[5];
    const float* v1    = (const float*)d_in[6];
    const float* w2    = (const float*)d_in[7];
    const float* g2    = (const float*)d_in[8];
    const float* be2   = (const float*)d_in[9];
    const float* m2    = (const float*)d_in[10];
    const float* v2    = (const float*)d_in[11];
    const float* wfc   = (const float*)d_in[12];
    const float* g3    = (const float*)d_in[13];
    const float* be3   = (const float*)d_in[14];
    const float* m3    = (const float*)d_in[15];
    const float* v3    = (const float*)d_in[16];
    const float* wlast = (const float*)d_in[17];
    const float* blast = (const float*)d_in[18];
    float* out = (float*)d_out;

    // 288 + 516*36 + 32 + 32 + 516 = 19444 prep tasks
    prep_kernel<<<76, 256>>>(w2, wfc, g1, be1, m1, v1,
                             g2, be2, m2, v2, g3, be3, m3, v3);
    fused_kernel<<<8192, 256>>>(x, w0, b0, wlast, blast, out);
}